// round 13
// baseline (speedup 1.0000x reference)
#include <cuda_runtime.h>
#include <cstdint>

// GraphReversePool: out[b, v] = x[b, v2c[v]]
//   x   : [BATCH, N_CLUSTERS] fp32   (d_in[0])
//   v2c : [VERTICES] int32           (d_in[1])
//   out : [BATCH, VERTICES] fp32
//
// R12: R11 schedule (grid=batch, 1 row/CTA, cp.async.bulk staging,
// 2 CTAs/SM, u16 indices as 2x LDG.64, coalesced STG.128.cs) with the
// v2c->u16 pack FUSED into the gather kernel: first 13 CTAs pack (hidden
// under the wave-1 row-DMA burst), all CTAs spin on a release/acquire
// counter before gathering. Counter reset per replay via cudaMemsetAsync.

#define BLOCK_THREADS 1024
#define MAX_VERTICES_U16 131072

__device__ __align__(16) unsigned short g_v2c16[MAX_VERTICES_U16];
__device__ unsigned int g_pack_ctr;

__device__ __forceinline__ uint32_t smem_u32(const void* p) {
    return (uint32_t)__cvta_generic_to_shared(p);
}

__global__ __launch_bounds__(BLOCK_THREADS, 2)
void graph_reverse_pool_kernel(const float* __restrict__ x,
                               const int*   __restrict__ v2c,
                               float*       __restrict__ out,
                               int batch, int n_clusters, int n_vertices,
                               int use_u16, int n_packers)
{
    extern __shared__ __align__(16) unsigned char smem_raw[];
    float* srow = reinterpret_cast<float*>(smem_raw);

    const int b = blockIdx.x;

    const int row_bytes = n_clusters * 4;
    const int mbar_off  = (row_bytes + 15) & ~15;
    uint64_t* mbar = reinterpret_cast<uint64_t*>(smem_raw + mbar_off);
    const uint32_t mbar_addr = smem_u32(mbar);

    const float* __restrict__ xrow = x + (size_t)b * n_clusters;

    // ---- Packer CTAs: convert v2c (int32) -> g_v2c16 (u16), then signal ----
    if (use_u16 && b < n_packers) {
        const int n8 = n_vertices >> 3;                     // uint4 groups of 8 idx
        const int i = b * BLOCK_THREADS + threadIdx.x;
        if (i < n8) {
            const int4 a0 = reinterpret_cast<const int4*>(v2c)[2 * i];
            const int4 a1 = reinterpret_cast<const int4*>(v2c)[2 * i + 1];
            uint4 p;
            p.x = (uint32_t)(a0.x & 0xFFFF) | ((uint32_t)a0.y << 16);
            p.y = (uint32_t)(a0.z & 0xFFFF) | ((uint32_t)a0.w << 16);
            p.z = (uint32_t)(a1.x & 0xFFFF) | ((uint32_t)a1.y << 16);
            p.w = (uint32_t)(a1.z & 0xFFFF) | ((uint32_t)a1.w << 16);
            reinterpret_cast<uint4*>(g_v2c16)[i] = p;
        }
        // scalar tail (n_vertices % 8) handled by CTA 0
        if (b == 0 && threadIdx.x < 8) {
            const int t = (n8 << 3) + threadIdx.x;
            if (t < n_vertices) g_v2c16[t] = (unsigned short)v2c[t];
        }
        __syncthreads();
        if (threadIdx.x == 0) {
            __threadfence();                                // release packed data
            atomicAdd(&g_pack_ctr, 1u);
        }
    }

    // ---- Stage x row into smem with one bulk DMA (overlaps packing) ----
    const bool can_bulk = ((row_bytes & 15) == 0) &&
                          ((((uintptr_t)xrow) & 15) == 0);
    if (can_bulk) {
        if (threadIdx.x == 0) {
            asm volatile("mbarrier.init.shared.b64 [%0], 1;"
                         :: "r"(mbar_addr) : "memory");
            asm volatile("fence.proxy.async.shared::cta;" ::: "memory");
        }
        __syncthreads();
        if (threadIdx.x == 0) {
            asm volatile("mbarrier.arrive.expect_tx.shared.b64 _, [%0], %1;"
                         :: "r"(mbar_addr), "r"((uint32_t)row_bytes) : "memory");
            asm volatile("cp.async.bulk.shared::cta.global.mbarrier::complete_tx::bytes "
                         "[%0], [%1], %2, [%3];"
                         :: "r"(smem_u32(srow)), "l"(xrow),
                            "r"((uint32_t)row_bytes), "r"(mbar_addr)
                         : "memory");
        }
        uint32_t done = 0;
        while (!done) {
            asm volatile(
                "{\n\t.reg .pred p;\n\t"
                "mbarrier.try_wait.parity.acquire.cta.shared::cta.b64 p, [%1], 0, 0x989680;\n\t"
                "selp.b32 %0, 1, 0, p;\n\t}"
                : "=r"(done) : "r"(mbar_addr) : "memory");
        }
    } else {
        for (int i = threadIdx.x; i < n_clusters; i += BLOCK_THREADS)
            srow[i] = xrow[i];
        __syncthreads();
    }

    // ---- Wait for packing completion (acquire) ----
    if (use_u16) {
        if (threadIdx.x == 0) {
            while (*(volatile unsigned int*)&g_pack_ctr < (unsigned int)n_packers) {
                __nanosleep(64);
            }
        }
        __syncthreads();
        __threadfence();                                    // acquire packed data
    }

    float4* __restrict__ o = reinterpret_cast<float4*>(out + (size_t)b * n_vertices);
    const int S = BLOCK_THREADS;
    const int nv4 = n_vertices >> 2;                        // 25000 for 100000

    if (use_u16) {
        // ---- Gather: 2x LDG.64 (4 u16 idx each) -> 8x LDS -> 2x STG.128.cs ----
        const uint2* __restrict__ idx4 = reinterpret_cast<const uint2*>(g_v2c16);

        int v = threadIdx.x;
        while (v + S < nv4) {
            const uint2 w0 = idx4[v];
            const uint2 w1 = idx4[v + S];
            float4 a0, a1;
            a0.x = srow[w0.x & 0xFFFF]; a0.y = srow[w0.x >> 16];
            a0.z = srow[w0.y & 0xFFFF]; a0.w = srow[w0.y >> 16];
            a1.x = srow[w1.x & 0xFFFF]; a1.y = srow[w1.x >> 16];
            a1.z = srow[w1.y & 0xFFFF]; a1.w = srow[w1.y >> 16];
            __stcs(&o[v],     a0);
            __stcs(&o[v + S], a1);
            v += 2 * S;
        }
        if (v < nv4) {
            const uint2 w = idx4[v];
            float4 a;
            a.x = srow[w.x & 0xFFFF]; a.y = srow[w.x >> 16];
            a.z = srow[w.y & 0xFFFF]; a.w = srow[w.y >> 16];
            __stcs(&o[v], a);
        }
        for (int t = (nv4 << 2) + threadIdx.x; t < n_vertices; t += S) {
            out[(size_t)b * n_vertices + t] = srow[v2c[t]];
        }
    } else {
        // fallback: int32 index path (exact R5)
        const int4* __restrict__ v2c4 = reinterpret_cast<const int4*>(v2c);
        int v = threadIdx.x;
        while (v + S < nv4) {
            const int4 c0 = v2c4[v];
            const int4 c1 = v2c4[v + S];
            float4 a0, a1;
            a0.x = srow[c0.x]; a0.y = srow[c0.y]; a0.z = srow[c0.z]; a0.w = srow[c0.w];
            a1.x = srow[c1.x]; a1.y = srow[c1.y]; a1.z = srow[c1.z]; a1.w = srow[c1.w];
            __stcs(&o[v],     a0);
            __stcs(&o[v + S], a1);
            v += 2 * S;
        }
        if (v < nv4) {
            const int4 c = v2c4[v];
            float4 a;
            a.x = srow[c.x]; a.y = srow[c.y]; a.z = srow[c.z]; a.w = srow[c.w];
            __stcs(&o[v], a);
        }
        for (int t = (nv4 << 2) + threadIdx.x; t < n_vertices; t += S) {
            out[(size_t)b * n_vertices + t] = srow[v2c[t]];
        }
    }
}

extern "C" void kernel_launch(void* const* d_in, const int* in_sizes, int n_in,
                              void* d_out, int out_size)
{
    const float* x   = (const float*)d_in[0];
    const int*   v2c = (const int*)  d_in[1];
    float*       out = (float*)d_out;

    const int n_vertices = in_sizes[1];                  // 100000
    const int batch      = out_size / n_vertices;        // 1024
    const int n_clusters = in_sizes[0] / batch;          // 25000

    const int row_bytes  = n_clusters * (int)sizeof(float);      // 100000
    const int smem_bytes = ((row_bytes + 15) & ~15) + 16;        // row + mbarrier

    static void* ctr_addr = nullptr;
    if (ctr_addr == nullptr) {
        cudaFuncSetAttribute(graph_reverse_pool_kernel,
                             cudaFuncAttributeMaxDynamicSharedMemorySize,
                             smem_bytes);
        cudaGetSymbolAddress(&ctr_addr, g_pack_ctr);
    }

    const int use_u16 = (n_clusters <= 65535) &&
                        (n_vertices <= MAX_VERTICES_U16) &&
                        ((n_vertices & 3) == 0);

    int n_packers = 0;
    if (use_u16) {
        const int n8 = n_vertices >> 3;
        n_packers = (n8 + BLOCK_THREADS - 1) / BLOCK_THREADS;   // 13 for 100000
        if (n_packers < 1) n_packers = 1;
        if (n_packers > batch) n_packers = batch;
        cudaMemsetAsync(ctr_addr, 0, sizeof(unsigned int));     // reset per replay
    }

    graph_reverse_pool_kernel<<<batch, BLOCK_THREADS, smem_bytes>>>(
        x, v2c, out, batch, n_clusters, n_vertices,
        use_u16 ? 1 : 0, n_packers);
}

// round 14
// speedup vs baseline: 1.0389x; 1.0389x over previous
#include <cuda_runtime.h>
#include <cstdint>

// GraphReversePool: out[b, v] = x[b, v2c[v]]
//   x   : [BATCH, N_CLUSTERS] fp32   (d_in[0])
//   v2c : [VERTICES] int32           (d_in[1])
//   out : [BATCH, VERTICES] fp32
//
// R13 = R11 (best: 91.8us) + explicit next-iteration index prefetch.
//   - grid=batch, 1 row/CTA staged via one cp.async.bulk, 2 CTAs/SM
//   - separate tiny pack kernel: v2c int32 -> u16 (halves idx traffic)
//   - gather: 2x LDG.64 (u16 x4) -> 8x LDS.32 -> 2x coalesced STG.128.cs,
//     with next iteration's uint2 pair loaded before consuming the current
//     one (hides ~240cyc L2 idx latency; ptxas won't pipeline at 32-reg cap).

#define BLOCK_THREADS 1024
#define MAX_VERTICES_U16 131072

__device__ __align__(16) unsigned short g_v2c16[MAX_VERTICES_U16];

__device__ __forceinline__ uint32_t smem_u32(const void* p) {
    return (uint32_t)__cvta_generic_to_shared(p);
}

__global__ void pack_v2c_kernel(const int* __restrict__ v2c, int n)
{
    // pack 8 int32 -> 8 u16 (one uint4 store) per thread
    const int n8 = n >> 3;
    int i = blockIdx.x * blockDim.x + threadIdx.x;
    if (i < n8) {
        const int4 a = reinterpret_cast<const int4*>(v2c)[2 * i];
        const int4 b = reinterpret_cast<const int4*>(v2c)[2 * i + 1];
        uint4 p;
        p.x = (uint32_t)(a.x & 0xFFFF) | ((uint32_t)a.y << 16);
        p.y = (uint32_t)(a.z & 0xFFFF) | ((uint32_t)a.w << 16);
        p.z = (uint32_t)(b.x & 0xFFFF) | ((uint32_t)b.y << 16);
        p.w = (uint32_t)(b.z & 0xFFFF) | ((uint32_t)b.w << 16);
        reinterpret_cast<uint4*>(g_v2c16)[i] = p;
    }
    // scalar tail
    const int t = (n8 << 3) + i;
    if (i < 8 && t < n) {
        g_v2c16[t] = (unsigned short)v2c[t];
    }
}

__global__ __launch_bounds__(BLOCK_THREADS, 2)
void graph_reverse_pool_kernel(const float* __restrict__ x,
                               const int*   __restrict__ v2c,
                               float*       __restrict__ out,
                               int batch, int n_clusters, int n_vertices,
                               int use_u16)
{
    extern __shared__ __align__(16) unsigned char smem_raw[];
    float* srow = reinterpret_cast<float*>(smem_raw);

    const int b = blockIdx.x;

    const int row_bytes = n_clusters * 4;
    const int mbar_off  = (row_bytes + 15) & ~15;
    uint64_t* mbar = reinterpret_cast<uint64_t*>(smem_raw + mbar_off);
    const uint32_t mbar_addr = smem_u32(mbar);

    const float* __restrict__ xrow = x + (size_t)b * n_clusters;

    // ---- Stage x row into smem with one bulk DMA ----
    const bool can_bulk = ((row_bytes & 15) == 0) &&
                          ((((uintptr_t)xrow) & 15) == 0);
    if (can_bulk) {
        if (threadIdx.x == 0) {
            asm volatile("mbarrier.init.shared.b64 [%0], 1;"
                         :: "r"(mbar_addr) : "memory");
            asm volatile("fence.proxy.async.shared::cta;" ::: "memory");
        }
        __syncthreads();
        if (threadIdx.x == 0) {
            asm volatile("mbarrier.arrive.expect_tx.shared.b64 _, [%0], %1;"
                         :: "r"(mbar_addr), "r"((uint32_t)row_bytes) : "memory");
            asm volatile("cp.async.bulk.shared::cta.global.mbarrier::complete_tx::bytes "
                         "[%0], [%1], %2, [%3];"
                         :: "r"(smem_u32(srow)), "l"(xrow),
                            "r"((uint32_t)row_bytes), "r"(mbar_addr)
                         : "memory");
        }
        uint32_t done = 0;
        while (!done) {
            asm volatile(
                "{\n\t.reg .pred p;\n\t"
                "mbarrier.try_wait.parity.acquire.cta.shared::cta.b64 p, [%1], 0, 0x989680;\n\t"
                "selp.b32 %0, 1, 0, p;\n\t}"
                : "=r"(done) : "r"(mbar_addr) : "memory");
        }
    } else {
        for (int i = threadIdx.x; i < n_clusters; i += BLOCK_THREADS)
            srow[i] = xrow[i];
        __syncthreads();
    }

    float4* __restrict__ o = reinterpret_cast<float4*>(out + (size_t)b * n_vertices);
    const int S = BLOCK_THREADS;
    const int nv4 = n_vertices >> 2;           // 25000 (exact for 100000)

    if (use_u16) {
        // ---- Gather: prefetched 2x LDG.64 -> 8x LDS -> 2x STG.128.cs ----
        const uint2* __restrict__ idx4 = reinterpret_cast<const uint2*>(g_v2c16);

        int v = threadIdx.x;
        if (v + S < nv4) {
            uint2 w0 = idx4[v];
            uint2 w1 = idx4[v + S];
            while (true) {
                const int vn = v + 2 * S;
                uint2 n0, n1;
                const bool more = (vn + S < nv4);
                if (more) {                     // prefetch next pair
                    n0 = idx4[vn];
                    n1 = idx4[vn + S];
                }
                float4 a0, a1;
                a0.x = srow[w0.x & 0xFFFF]; a0.y = srow[w0.x >> 16];
                a0.z = srow[w0.y & 0xFFFF]; a0.w = srow[w0.y >> 16];
                a1.x = srow[w1.x & 0xFFFF]; a1.y = srow[w1.x >> 16];
                a1.z = srow[w1.y & 0xFFFF]; a1.w = srow[w1.y >> 16];
                __stcs(&o[v],     a0);
                __stcs(&o[v + S], a1);
                if (!more) break;
                v = vn;
                w0 = n0;
                w1 = n1;
            }
            v += 2 * S;
        }
        if (v < nv4) {
            const uint2 w = idx4[v];
            float4 a;
            a.x = srow[w.x & 0xFFFF]; a.y = srow[w.x >> 16];
            a.z = srow[w.y & 0xFFFF]; a.w = srow[w.y >> 16];
            __stcs(&o[v], a);
        }
        // scalar tail (dead for 100000, kept for safety)
        for (int t = (nv4 << 2) + threadIdx.x; t < n_vertices; t += S) {
            out[(size_t)b * n_vertices + t] = srow[v2c[t]];
        }
    } else {
        // fallback: int32 index path (exact R5)
        const int4* __restrict__ v2c4 = reinterpret_cast<const int4*>(v2c);
        int v = threadIdx.x;
        while (v + S < nv4) {
            const int4 c0 = v2c4[v];
            const int4 c1 = v2c4[v + S];
            float4 a0, a1;
            a0.x = srow[c0.x]; a0.y = srow[c0.y]; a0.z = srow[c0.z]; a0.w = srow[c0.w];
            a1.x = srow[c1.x]; a1.y = srow[c1.y]; a1.z = srow[c1.z]; a1.w = srow[c1.w];
            __stcs(&o[v],     a0);
            __stcs(&o[v + S], a1);
            v += 2 * S;
        }
        if (v < nv4) {
            const int4 c = v2c4[v];
            float4 a;
            a.x = srow[c.x]; a.y = srow[c.y]; a.z = srow[c.z]; a.w = srow[c.w];
            __stcs(&o[v], a);
        }
        for (int t = (nv4 << 2) + threadIdx.x; t < n_vertices; t += S) {
            out[(size_t)b * n_vertices + t] = srow[v2c[t]];
        }
    }
}

extern "C" void kernel_launch(void* const* d_in, const int* in_sizes, int n_in,
                              void* d_out, int out_size)
{
    const float* x   = (const float*)d_in[0];
    const int*   v2c = (const int*)  d_in[1];
    float*       out = (float*)d_out;

    const int n_vertices = in_sizes[1];                  // 100000
    const int batch      = out_size / n_vertices;        // 1024
    const int n_clusters = in_sizes[0] / batch;          // 25000

    const int row_bytes  = n_clusters * (int)sizeof(float);      // 100000
    const int smem_bytes = ((row_bytes + 15) & ~15) + 16;        // row + mbarrier

    static bool attr_set = false;
    if (!attr_set) {
        cudaFuncSetAttribute(graph_reverse_pool_kernel,
                             cudaFuncAttributeMaxDynamicSharedMemorySize,
                             smem_bytes);
        attr_set = true;
    }

    const int use_u16 = (n_clusters <= 65535) &&
                        (n_vertices <= MAX_VERTICES_U16) &&
                        ((n_vertices & 3) == 0);

    if (use_u16) {
        const int n8 = (n_vertices + 7) / 8;
        pack_v2c_kernel<<<(n8 + 255) / 256, 256>>>(v2c, n_vertices);
    }

    graph_reverse_pool_kernel<<<batch, BLOCK_THREADS, smem_bytes>>>(
        x, v2c, out, batch, n_clusters, n_vertices, use_u16 ? 1 : 0);
}

// round 15
// speedup vs baseline: 1.0472x; 1.0080x over previous
#include <cuda_runtime.h>
#include <cstdint>

// GraphReversePool: out[b, v] = x[b, v2c[v]]
//   x   : [BATCH, N_CLUSTERS] fp32   (d_in[0])
//   v2c : [VERTICES] int32           (d_in[1])
//   out : [BATCH, VERTICES] fp32
//
// R14 = R11 (best: 91.8us, gather body proven at its LSU/DRAM floor) + PDL:
//   - pack kernel (v2c int32 -> u16) launched normally
//   - gather kernel launched with ProgrammaticStreamSerialization so it
//     starts WHILE pack runs; each CTA issues its 100 KB row cp.async.bulk
//     immediately and only calls cudaGridDependencySynchronize() after the
//     staging wait, hiding the pack kernel + launch gap (~2.6us) entirely.

#define BLOCK_THREADS 1024
#define MAX_VERTICES_U16 131072

__device__ __align__(16) unsigned short g_v2c16[MAX_VERTICES_U16];

__device__ __forceinline__ uint32_t smem_u32(const void* p) {
    return (uint32_t)__cvta_generic_to_shared(p);
}

__global__ void pack_v2c_kernel(const int* __restrict__ v2c, int n)
{
    // pack 8 int32 -> 8 u16 (one uint4 store) per thread
    const int n8 = n >> 3;
    int i = blockIdx.x * blockDim.x + threadIdx.x;
    if (i < n8) {
        const int4 a = reinterpret_cast<const int4*>(v2c)[2 * i];
        const int4 b = reinterpret_cast<const int4*>(v2c)[2 * i + 1];
        uint4 p;
        p.x = (uint32_t)(a.x & 0xFFFF) | ((uint32_t)a.y << 16);
        p.y = (uint32_t)(a.z & 0xFFFF) | ((uint32_t)a.w << 16);
        p.z = (uint32_t)(b.x & 0xFFFF) | ((uint32_t)b.y << 16);
        p.w = (uint32_t)(b.z & 0xFFFF) | ((uint32_t)b.w << 16);
        reinterpret_cast<uint4*>(g_v2c16)[i] = p;
    }
    // scalar tail
    const int t = (n8 << 3) + i;
    if (i < 8 && t < n) {
        g_v2c16[t] = (unsigned short)v2c[t];
    }
}

__global__ __launch_bounds__(BLOCK_THREADS, 2)
void graph_reverse_pool_kernel(const float* __restrict__ x,
                               const int*   __restrict__ v2c,
                               float*       __restrict__ out,
                               int batch, int n_clusters, int n_vertices,
                               int use_u16)
{
    extern __shared__ __align__(16) unsigned char smem_raw[];
    float* srow = reinterpret_cast<float*>(smem_raw);

    const int b = blockIdx.x;

    const int row_bytes = n_clusters * 4;
    const int mbar_off  = (row_bytes + 15) & ~15;
    uint64_t* mbar = reinterpret_cast<uint64_t*>(smem_raw + mbar_off);
    const uint32_t mbar_addr = smem_u32(mbar);

    const float* __restrict__ xrow = x + (size_t)b * n_clusters;

    // ---- Stage x row into smem with one bulk DMA (runs under pack kernel) ----
    const bool can_bulk = ((row_bytes & 15) == 0) &&
                          ((((uintptr_t)xrow) & 15) == 0);
    if (can_bulk) {
        if (threadIdx.x == 0) {
            asm volatile("mbarrier.init.shared.b64 [%0], 1;"
                         :: "r"(mbar_addr) : "memory");
            asm volatile("fence.proxy.async.shared::cta;" ::: "memory");
        }
        __syncthreads();
        if (threadIdx.x == 0) {
            asm volatile("mbarrier.arrive.expect_tx.shared.b64 _, [%0], %1;"
                         :: "r"(mbar_addr), "r"((uint32_t)row_bytes) : "memory");
            asm volatile("cp.async.bulk.shared::cta.global.mbarrier::complete_tx::bytes "
                         "[%0], [%1], %2, [%3];"
                         :: "r"(smem_u32(srow)), "l"(xrow),
                            "r"((uint32_t)row_bytes), "r"(mbar_addr)
                         : "memory");
        }
        uint32_t done = 0;
        while (!done) {
            asm volatile(
                "{\n\t.reg .pred p;\n\t"
                "mbarrier.try_wait.parity.acquire.cta.shared::cta.b64 p, [%1], 0, 0x989680;\n\t"
                "selp.b32 %0, 1, 0, p;\n\t}"
                : "=r"(done) : "r"(mbar_addr) : "memory");
        }
    } else {
        for (int i = threadIdx.x; i < n_clusters; i += BLOCK_THREADS)
            srow[i] = xrow[i];
        __syncthreads();
    }

    // ---- PDL: ensure the pack kernel has fully completed before reading
    //      g_v2c16. By now the ~5us staging DMA has hidden the ~2us pack. ----
    if (use_u16) {
        cudaGridDependencySynchronize();
    }

    float4* __restrict__ o = reinterpret_cast<float4*>(out + (size_t)b * n_vertices);
    const int S = BLOCK_THREADS;
    const int nv4 = n_vertices >> 2;           // 25000 (exact for 100000)

    if (use_u16) {
        // ---- Gather: 2x LDG.64 (u16 x4 idx) -> 8x LDS -> 2x STG.128.cs ----
        const uint2* __restrict__ idx4 = reinterpret_cast<const uint2*>(g_v2c16);

        int v = threadIdx.x;
        while (v + S < nv4) {
            const uint2 w0 = idx4[v];
            const uint2 w1 = idx4[v + S];
            float4 a0, a1;
            a0.x = srow[w0.x & 0xFFFF]; a0.y = srow[w0.x >> 16];
            a0.z = srow[w0.y & 0xFFFF]; a0.w = srow[w0.y >> 16];
            a1.x = srow[w1.x & 0xFFFF]; a1.y = srow[w1.x >> 16];
            a1.z = srow[w1.y & 0xFFFF]; a1.w = srow[w1.y >> 16];
            __stcs(&o[v],     a0);
            __stcs(&o[v + S], a1);
            v += 2 * S;
        }
        if (v < nv4) {
            const uint2 w = idx4[v];
            float4 a;
            a.x = srow[w.x & 0xFFFF]; a.y = srow[w.x >> 16];
            a.z = srow[w.y & 0xFFFF]; a.w = srow[w.y >> 16];
            __stcs(&o[v], a);
        }
        // scalar tail (dead for 100000, kept for safety)
        for (int t = (nv4 << 2) + threadIdx.x; t < n_vertices; t += S) {
            out[(size_t)b * n_vertices + t] = srow[v2c[t]];
        }
    } else {
        // fallback: int32 index path (exact R5)
        const int4* __restrict__ v2c4 = reinterpret_cast<const int4*>(v2c);
        int v = threadIdx.x;
        while (v + S < nv4) {
            const int4 c0 = v2c4[v];
            const int4 c1 = v2c4[v + S];
            float4 a0, a1;
            a0.x = srow[c0.x]; a0.y = srow[c0.y]; a0.z = srow[c0.z]; a0.w = srow[c0.w];
            a1.x = srow[c1.x]; a1.y = srow[c1.y]; a1.z = srow[c1.z]; a1.w = srow[c1.w];
            __stcs(&o[v],     a0);
            __stcs(&o[v + S], a1);
            v += 2 * S;
        }
        if (v < nv4) {
            const int4 c = v2c4[v];
            float4 a;
            a.x = srow[c.x]; a.y = srow[c.y]; a.z = srow[c.z]; a.w = srow[c.w];
            __stcs(&o[v], a);
        }
        for (int t = (nv4 << 2) + threadIdx.x; t < n_vertices; t += S) {
            out[(size_t)b * n_vertices + t] = srow[v2c[t]];
        }
    }
}

extern "C" void kernel_launch(void* const* d_in, const int* in_sizes, int n_in,
                              void* d_out, int out_size)
{
    const float* x   = (const float*)d_in[0];
    const int*   v2c = (const int*)  d_in[1];
    float*       out = (float*)d_out;

    const int n_vertices = in_sizes[1];                  // 100000
    const int batch      = out_size / n_vertices;        // 1024
    const int n_clusters = in_sizes[0] / batch;          // 25000

    const int row_bytes  = n_clusters * (int)sizeof(float);      // 100000
    const int smem_bytes = ((row_bytes + 15) & ~15) + 16;        // row + mbarrier

    static bool attr_set = false;
    if (!attr_set) {
        cudaFuncSetAttribute(graph_reverse_pool_kernel,
                             cudaFuncAttributeMaxDynamicSharedMemorySize,
                             smem_bytes);
        attr_set = true;
    }

    const int use_u16 = (n_clusters <= 65535) &&
                        (n_vertices <= MAX_VERTICES_U16) &&
                        ((n_vertices & 3) == 0);

    if (use_u16) {
        const int n8 = (n_vertices + 7) / 8;
        pack_v2c_kernel<<<(n8 + 255) / 256, 256>>>(v2c, n_vertices);

        // Launch gather with Programmatic Dependent Launch: starts while
        // pack runs; CTAs sync on pack completion only after their row DMA.
        cudaLaunchConfig_t cfg = {};
        cfg.gridDim  = dim3((unsigned)batch);
        cfg.blockDim = dim3(BLOCK_THREADS);
        cfg.dynamicSmemBytes = (size_t)smem_bytes;
        cfg.stream = 0;
        cudaLaunchAttribute attrs[1];
        attrs[0].id = cudaLaunchAttributeProgrammaticStreamSerialization;
        attrs[0].val.programmaticStreamSerializationAllowed = 1;
        cfg.attrs = attrs;
        cfg.numAttrs = 1;
        cudaError_t e = cudaLaunchKernelEx(&cfg, graph_reverse_pool_kernel,
                                           x, v2c, out,
                                           batch, n_clusters, n_vertices,
                                           (int)1);
        if (e != cudaSuccess) {
            // fallback: plain serialized launch
            graph_reverse_pool_kernel<<<batch, BLOCK_THREADS, smem_bytes>>>(
                x, v2c, out, batch, n_clusters, n_vertices, 1);
        }
    } else {
        graph_reverse_pool_kernel<<<batch, BLOCK_THREADS, smem_bytes>>>(
            x, v2c, out, batch, n_clusters, n_vertices, 0);
    }
}